// round 1
// baseline (speedup 1.0000x reference)
#include <cuda_runtime.h>
#include <cstdint>
#include <cstddef>

#define T_STEPS 512
#define BATCH   64
#define DIN     128
#define DH      1024
#define DOUT    256
#define RNK     64

// Scratch for zi = x @ Wi^T  (static device global: allocation-free)
__device__ float g_zi[(size_t)T_STEPS * BATCH * DH];

// ---------------------------------------------------------------------------
// Generic fp32 GEMM:  C[M,N] = A[M,K] * B[N,K]^T (+ bias[n])
// BM=128, BN=64, BK=16, 256 threads, 8x4 per thread. All dims divide exactly.
// ---------------------------------------------------------------------------
#define BM 128
#define BN 64
#define BKK 16

__global__ __launch_bounds__(256) void gemm_nt_kernel(
    const float* __restrict__ A, const float* __restrict__ B,
    float* __restrict__ C, const float* __restrict__ bias,
    int M, int N, int K)
{
    __shared__ float As[BKK][BM + 4];
    __shared__ float Bs[BKK][BN + 4];

    const int tid = threadIdx.x;
    const int ty  = tid >> 4;   // 0..15  (M groups of 8)
    const int tx  = tid & 15;   // 0..15  (N groups of 4)

    const float* Ab = A + (size_t)blockIdx.x * BM * K;
    const float* Bb = B + (size_t)blockIdx.y * BN * K;

    float acc[8][4];
#pragma unroll
    for (int i = 0; i < 8; i++)
#pragma unroll
        for (int j = 0; j < 4; j++) acc[i][j] = 0.f;

    const int i0 = tid * 2, i1 = tid * 2 + 1;
    const int ar0 = i0 >> 2, ac0 = (i0 & 3) * 4;
    const int ar1 = i1 >> 2, ac1 = (i1 & 3) * 4;
    const int br  = tid >> 2, bc  = (tid & 3) * 4;

    float4 pa0 = *(const float4*)&Ab[(size_t)ar0 * K + ac0];
    float4 pa1 = *(const float4*)&Ab[(size_t)ar1 * K + ac1];
    float4 pb0 = *(const float4*)&Bb[(size_t)br  * K + bc];

    for (int kt = 0; kt < K; kt += BKK) {
        __syncthreads();
        As[ac0 + 0][ar0] = pa0.x; As[ac0 + 1][ar0] = pa0.y;
        As[ac0 + 2][ar0] = pa0.z; As[ac0 + 3][ar0] = pa0.w;
        As[ac1 + 0][ar1] = pa1.x; As[ac1 + 1][ar1] = pa1.y;
        As[ac1 + 2][ar1] = pa1.z; As[ac1 + 3][ar1] = pa1.w;
        Bs[bc  + 0][br ] = pb0.x; Bs[bc  + 1][br ] = pb0.y;
        Bs[bc  + 2][br ] = pb0.z; Bs[bc  + 3][br ] = pb0.w;
        __syncthreads();

        if (kt + BKK < K) {
            pa0 = *(const float4*)&Ab[(size_t)ar0 * K + kt + BKK + ac0];
            pa1 = *(const float4*)&Ab[(size_t)ar1 * K + kt + BKK + ac1];
            pb0 = *(const float4*)&Bb[(size_t)br  * K + kt + BKK + bc];
        }

#pragma unroll
        for (int k = 0; k < BKK; k++) {
            float ra[8], rb[4];
            *(float4*)&ra[0] = *(const float4*)&As[k][ty * 8];
            *(float4*)&ra[4] = *(const float4*)&As[k][ty * 8 + 4];
            *(float4*)&rb[0] = *(const float4*)&Bs[k][tx * 4];
#pragma unroll
            for (int i = 0; i < 8; i++)
#pragma unroll
                for (int j = 0; j < 4; j++)
                    acc[i][j] += ra[i] * rb[j];
        }
    }

    const int m0 = blockIdx.x * BM + ty * 8;
    const int n0 = blockIdx.y * BN + tx * 4;
    float bj0 = 0.f, bj1 = 0.f, bj2 = 0.f, bj3 = 0.f;
    if (bias) { bj0 = bias[n0]; bj1 = bias[n0 + 1]; bj2 = bias[n0 + 2]; bj3 = bias[n0 + 3]; }
#pragma unroll
    for (int i = 0; i < 8; i++) {
        float4 v = make_float4(acc[i][0] + bj0, acc[i][1] + bj1,
                               acc[i][2] + bj2, acc[i][3] + bj3);
        *(float4*)&C[(size_t)(m0 + i) * N + n0] = v;
    }
}

// ---------------------------------------------------------------------------
// Recurrence kernel: 16 clusters x 8 CTAs. Cluster c owns batches [4c,4c+4).
// CTA rank rk owns h-slice [128rk, 128rk+128). V/U slices SMEM-resident.
// Per step: local partial s = h_slice @ V_slice^T  -> cluster all-reduce of
// s (rank bottleneck, 1KB/CTA) via DSMEM -> h_new = relu(s @ U_slice^T + bh + zi).
// One barrier.cluster per step (double-buffered partials).
// ---------------------------------------------------------------------------
#define CLUSTER 8
#define SLICE   128      // DH / CLUSTER
#define BPC     4        // batches per cluster
#define NTHR    256

// float offsets inside dynamic smem
#define OFF_V   0                       // [64][129]
#define OFF_U   (OFF_V + 64 * 129)      // [128][65]
#define OFF_H   (OFF_U + 128 * 65)      // [128][4]   h (j-major, 4 batches)
#define OFF_P   (OFF_H + 128 * 4)       // [2][256]   partial s (double buffer)
#define OFF_SC  (OFF_P + 512)           // [256][4]   scratch
#define OFF_S   (OFF_SC + 1024)         // [256]      reduced s  (r*4+b)
#define OFF_BH  (OFF_S + 256)           // [128]
#define SMEM_FLOATS (OFF_BH + 128)      // 19008 floats = 76032 B
#define DYN_SMEM 122880                 // force 1 CTA/SM (2x122880 > 227KB)

__device__ __forceinline__ void cluster_sync_() {
    asm volatile("barrier.cluster.arrive.aligned;" ::: "memory");
    asm volatile("barrier.cluster.wait.aligned;" ::: "memory");
}

__global__ void __cluster_dims__(CLUSTER, 1, 1) __launch_bounds__(NTHR, 1)
rnn_recurrence_kernel(const float* __restrict__ V, const float* __restrict__ U,
                      const float* __restrict__ bh, const float* __restrict__ zi,
                      float* __restrict__ hidden)
{
    extern __shared__ float sm[];
    float* V_s  = sm + OFF_V;
    float* U_s  = sm + OFF_U;
    float* h_s  = sm + OFF_H;
    float* part = sm + OFF_P;
    float* scr  = sm + OFF_SC;
    float* s_s  = sm + OFF_S;
    float* bh_s = sm + OFF_BH;

    const int tid = threadIdx.x;
    uint32_t rk;
    asm("mov.u32 %0, %%cluster_ctarank;" : "=r"(rk));
    const int grp   = blockIdx.x / CLUSTER;   // 0..15
    const int bbase = grp * BPC;
    const int jbase = (int)rk * SLICE;

    // ---- load weights into SMEM (padded to kill bank conflicts) ----
    for (int i = tid; i < 64 * SLICE; i += NTHR) {
        int r = i / SLICE, j = i % SLICE;
        V_s[r * (SLICE + 1) + j] = V[r * DH + jbase + j];
    }
    for (int i = tid; i < SLICE * RNK; i += NTHR) {
        int j = i / RNK, r = i % RNK;
        U_s[j * (RNK + 1) + r] = U[(size_t)(jbase + j) * RNK + r];
    }
    if (tid < SLICE) bh_s[tid] = bh[jbase + tid];
    for (int i = tid; i < SLICE * 4; i += NTHR) h_s[i] = 0.f;   // h0 = 0
    __syncthreads();

    // ---- precompute peer DSMEM addresses of 'part' ----
    uint32_t part_addr = (uint32_t)__cvta_generic_to_shared(part);
    uint32_t peer[CLUSTER];
#pragma unroll
    for (int p = 0; p < CLUSTER; p++)
        asm("mapa.shared::cluster.u32 %0, %1, %2;"
            : "=r"(peer[p]) : "r"(part_addr), "r"(p));

    const int r1 = tid & 63,  c1 = tid >> 6;   // GEMM1 mapping: (r, j-chunk)
    const int j2 = tid & 127, hf = tid >> 7;   // GEMM2 mapping: (j, r-half)

    const float*  vrow = &V_s[r1 * (SLICE + 1) + c1 * 32];
    const float4* hc   = (const float4*)&h_s[c1 * 32 * 4];
    const float*  urow = &U_s[j2 * (RNK + 1) + hf * 32];
    const float4* sc   = (const float4*)&s_s[hf * 32 * 4];

    for (int t = 0; t < T_STEPS; t++) {
        const int buf = t & 1;

        // prefetch zi for this step (consumed in epilogue; latency hidden)
        float z0 = 0.f, z1 = 0.f, z2 = 0.f, z3 = 0.f;
        if (hf == 0) {
            const float* zp = zi + ((size_t)(t * BATCH + bbase)) * DH + jbase + j2;
            z0 = zp[0]; z1 = zp[DH]; z2 = zp[2 * DH]; z3 = zp[3 * DH];
        }

        // ---- GEMM1: partial s[b][r] over local j-slice ----
        float a0 = 0.f, a1 = 0.f, a2 = 0.f, a3 = 0.f;
#pragma unroll 8
        for (int jj = 0; jj < 32; jj++) {
            float  v  = vrow[jj];
            float4 h4 = hc[jj];
            a0 += h4.x * v; a1 += h4.y * v; a2 += h4.z * v; a3 += h4.w * v;
        }
        ((float4*)scr)[tid] = make_float4(a0, a1, a2, a3);
        __syncthreads();
        if (tid < 64) {  // reduce 4 j-chunks -> partial[buf], layout r*4+b
            float4 s0 = ((float4*)scr)[tid];
            float4 s1 = ((float4*)scr)[tid + 64];
            float4 s2 = ((float4*)scr)[tid + 128];
            float4 s3 = ((float4*)scr)[tid + 192];
            ((float4*)(part + buf * 256))[tid] =
                make_float4(s0.x + s1.x + s2.x + s3.x, s0.y + s1.y + s2.y + s3.y,
                            s0.z + s1.z + s2.z + s3.z, s0.w + s1.w + s2.w + s3.w);
        }

        // ---- single cluster barrier per step (release/acquire semantics) ----
        cluster_sync_();

        // ---- pull-reduce s across 8 CTAs via DSMEM ----
        {
            float ssum = 0.f;
            uint32_t off = (uint32_t)((buf * 256 + tid) * 4);
#pragma unroll
            for (int p = 0; p < CLUSTER; p++) {
                float v;
                asm volatile("ld.shared::cluster.f32 %0, [%1];"
                             : "=f"(v) : "r"(peer[p] + off));
                ssum += v;
            }
            s_s[tid] = ssum;
        }
        __syncthreads();

        // ---- GEMM2: h_new[b][j] = relu(s @ U^T + bh + zi) ----
        float b0 = 0.f, b1 = 0.f, b2 = 0.f, b3 = 0.f;
#pragma unroll 8
        for (int rr = 0; rr < 32; rr++) {
            float  u  = urow[rr];
            float4 s4 = sc[rr];
            b0 += s4.x * u; b1 += s4.y * u; b2 += s4.z * u; b3 += s4.w * u;
        }
        if (hf) ((float4*)scr)[j2] = make_float4(b0, b1, b2, b3);
        __syncthreads();
        if (hf == 0) {
            float4 o  = ((float4*)scr)[j2];
            float  bb = bh_s[j2];
            float h0 = fmaxf(b0 + o.x + bb + z0, 0.f);
            float h1 = fmaxf(b1 + o.y + bb + z1, 0.f);
            float h2 = fmaxf(b2 + o.z + bb + z2, 0.f);
            float h3 = fmaxf(b3 + o.w + bb + z3, 0.f);
            ((float4*)h_s)[j2] = make_float4(h0, h1, h2, h3);
            float* hp = hidden + ((size_t)(t * BATCH + bbase)) * DH + jbase + j2;
            hp[0] = h0; hp[DH] = h1; hp[2 * DH] = h2; hp[3 * DH] = h3;
        }
        __syncthreads();   // h_s/scr ready & consumed before next iteration
    }
}

// ---------------------------------------------------------------------------
extern "C" void kernel_launch(void* const* d_in, const int* in_sizes, int n_in,
                              void* d_out, int out_size)
{
    const float* x  = (const float*)d_in[0];
    const float* Wi = (const float*)d_in[1];
    const float* U  = (const float*)d_in[2];
    const float* V  = (const float*)d_in[3];
    const float* bh = (const float*)d_in[4];
    const float* Wo = (const float*)d_in[5];
    const float* bo = (const float*)d_in[6];

    float* hidden = (float*)d_out;                                    // [T,B,DH]
    float* output = (float*)d_out + (size_t)T_STEPS * BATCH * DH;     // [T,B,DOUT]

    float* zi = nullptr;
    cudaGetSymbolAddress((void**)&zi, g_zi);

    cudaFuncSetAttribute(rnn_recurrence_kernel,
                         cudaFuncAttributeMaxDynamicSharedMemorySize, DYN_SMEM);

    // K1: zi = x @ Wi^T    (M=32768, N=1024, K=128)
    {
        dim3 grid(T_STEPS * BATCH / BM, DH / BN);
        gemm_nt_kernel<<<grid, 256>>>(x, Wi, zi, nullptr,
                                      T_STEPS * BATCH, DH, DIN);
    }

    // K2: recurrence (writes hidden)
    {
        rnn_recurrence_kernel<<<128, NTHR, DYN_SMEM>>>(V, U, bh, zi, hidden);
    }

    // K3: output = hidden @ Wo^T + bo   (M=32768, N=256, K=1024)
    {
        dim3 grid(T_STEPS * BATCH / BM, DOUT / BN);
        gemm_nt_kernel<<<grid, 256>>>(hidden, Wo, output, bo,
                                      T_STEPS * BATCH, DOUT, DH);
    }
}